// round 4
// baseline (speedup 1.0000x reference)
#include <cuda_runtime.h>

#define MASK  511
#define W_IMG 512
#define PLANE (512 * 512)

#define R_OUT     4                      // out rows per warp
#define WARPS     4
#define TILE_ROWS 16                     // out rows per block
#define OUT_COLS  60                     // out cols per block (lanes 1..30, 2 each)
#define TROWS     30                     // 16 + 2*7 halo
#define TCOLS     76                     // 75 used + 1 pad (even => 8B row alignment)
#define TPIX      (TROWS * TCOLS)        // 2280
#define FULLM     0xffffffffu

typedef unsigned long long u64;

__device__ __forceinline__ u64 pk(float a, float b) {
    u64 r; asm("mov.b64 %0, {%1, %2};" : "=l"(r) : "f"(a), "f"(b)); return r;
}
__device__ __forceinline__ void up2(u64 v, float& a, float& b) {
    asm("mov.b64 {%0, %1}, %2;" : "=f"(a), "=f"(b) : "l"(v));
}
__device__ __forceinline__ u64 fma2(u64 a, u64 b, u64 c) {
    u64 d; asm("fma.rn.f32x2 %0, %1, %2, %3;" : "=l"(d) : "l"(a), "l"(b), "l"(c)); return d;
}
__device__ __forceinline__ u64 mul2(u64 a, u64 b) {
    u64 d; asm("mul.rn.f32x2 %0, %1, %2;" : "=l"(d) : "l"(a), "l"(b)); return d;
}
__device__ __forceinline__ u64 add2(u64 a, u64 b) {
    u64 d; asm("add.rn.f32x2 %0, %1, %2;" : "=l"(d) : "l"(a), "l"(b)); return d;
}
__device__ __forceinline__ float fsqrt_ap(float x) {
    float r; asm("sqrt.approx.f32 %0, %1;" : "=f"(r) : "f"(x)); return r;
}
__device__ __forceinline__ float fex2(float x) {
    float r; asm("ex2.approx.f32 %0, %1;" : "=f"(r) : "f"(x)); return r;
}

#define NEG1 0xBF800000BF800000ULL               /* {-1.f,-1.f} */
#define KEXP (-0.48089834696298784f)             /* -log2(e)/3  */

// Process one horizontal offset ox for all oy. ODD = (ox odd).
// shy: base pointer for shifted-pair loads (already col-adjusted, 8B-aligned rows)
// xro/xgo/xbo: channel planes offset by (cx+ox) column
template<bool ODD>
__device__ __forceinline__ void process_ox(
    const float* __restrict__ shy,
    const float* __restrict__ xro, const float* __restrict__ xgo,
    const float* __restrict__ xbo,
    const u64* __restrict__ yreg, int r0t,
    u64* aW, u64* aR, u64* aG, u64* aB)
{
    for (int oy = -5; oy <= 5; ++oy) {
        const float* shr = shy + (r0t + 5 + oy) * TCOLS;

        u64 s[8];
        #pragma unroll
        for (int j = 0; j < 8; ++j) {
            float2 v = *(const float2*)&shr[j * TCOLS];
            u64 sh = pk(v.x, v.y);
            u64 d  = fma2(NEG1, sh, yreg[j]);        // own - shifted
            s[j]   = mul2(d, d);
        }

        u64 vs = add2(add2(s[0], s[1]), add2(s[2], s[3]));
        const int xrow0 = (r0t + 7 + oy) * TCOLS;

        #pragma unroll
        for (int k = 0; k < 4; ++k) {
            u64 v5 = add2(vs, s[k + 4]);
            if (k < 3) vs = fma2(NEG1, s[k], v5);     // slide window

            float a, b; up2(v5, a, b);
            float am = __shfl_up_sync  (FULLM, a, 1);
            float bm = __shfl_up_sync  (FULLM, b, 1);
            float ap = __shfl_down_sync(FULLM, a, 1);
            float bp = __shfl_down_sync(FULLM, b, 1);
            float t   = a + b;
            float d2e = ((am + bm) + t) + ap;         // cols cx-2..cx+2
            float d2o = (bm + t) + (ap + bp);         // cols cx-1..cx+3
            float we  = fex2(fsqrt_ap(d2e) * KEXP);
            float wo  = fex2(fsqrt_ap(d2o) * KEXP);
            u64  w2   = pk(we, wo);
            aW[k] = add2(aW[k], w2);

            const int xi = xrow0 + k * TCOLS;
            u64 xpr, xpg, xpb;
            if (ODD) {
                xpr = pk(xro[xi], xro[xi + 1]);
                xpg = pk(xgo[xi], xgo[xi + 1]);
                xpb = pk(xbo[xi], xbo[xi + 1]);
            } else {
                float2 vr = *(const float2*)&xro[xi];
                float2 vg = *(const float2*)&xgo[xi];
                float2 vb = *(const float2*)&xbo[xi];
                xpr = pk(vr.x, vr.y); xpg = pk(vg.x, vg.y); xpb = pk(vb.x, vb.y);
            }
            aR[k] = fma2(w2, xpr, aR[k]);
            aG[k] = fma2(w2, xpg, aG[k]);
            aB[k] = fma2(w2, xpb, aB[k]);
        }
    }
}

__global__ __launch_bounds__(32 * WARPS, 4)
void nlm_kernel(const float* __restrict__ x, float* __restrict__ out)
{
    __shared__ __align__(16) float smem[5 * TPIX];   // ys | ysB | xr | xg | xb
    float* ys  = smem;
    float* ysB = smem + TPIX;                        // ysB[r][c] = y[r][c+1]
    float* xr  = smem + 2 * TPIX;
    float* xg  = smem + 3 * TPIX;
    float* xb  = smem + 4 * TPIX;

    const int lane = threadIdx.x;
    const int warp = threadIdx.y;
    const int tid  = warp * 32 + lane;

    const int n       = blockIdx.z;
    const int rowBase = blockIdx.y * TILE_ROWS;
    const int colBase = blockIdx.x * OUT_COLS;
    const int rowTop  = rowBase - 7 + 512;
    const int colLeft = colBase - 8 + 512;

    const float* xbase = x + (size_t)n * 3 * PLANE;

    for (int idx = tid; idx < TPIX; idx += 32 * WARPS) {
        int r  = idx / TCOLS;
        int c  = idx - r * TCOLS;
        int gy = (rowTop + r) & MASK;
        int gx = (colLeft + c) & MASK;
        const float* p = xbase + gy * W_IMG + gx;
        float rv = p[0];
        float gv = p[PLANE];
        float bv = p[2 * PLANE];
        float rc = fminf(fmaxf(rv, 0.f), 1.f);
        float gc = fminf(fmaxf(gv, 0.f), 1.f);
        float bc = fminf(fmaxf(bv, 0.f), 1.f);
        float yv = 0.299f * rc + 0.587f * gc + 0.114f * bc;
        xr[idx] = rv; xg[idx] = gv; xb[idx] = bv; ys[idx] = yv;
        if (c) ysB[idx - 1] = yv;
    }
    __syncthreads();

    const int r0t = warp * R_OUT;          // warp's out-row start (tile row = +7)
    const int cx  = 6 + 2 * lane;          // own pair: tile cols (cx, cx+1)

    u64 yreg[8];                           // own pairs, template rows r0t+5..r0t+12
    #pragma unroll
    for (int j = 0; j < 8; ++j) {
        float2 v = *(const float2*)&ys[(r0t + 5 + j) * TCOLS + cx];
        yreg[j] = pk(v.x, v.y);
    }

    u64 aW[4], aR[4], aG[4], aB[4];
    #pragma unroll
    for (int k = 0; k < 4; ++k) { aW[k] = 0ULL; aR[k] = 0ULL; aG[k] = 0ULL; aB[k] = 0ULL; }

    for (int ox = -4; ox <= 4; ox += 2)    // even ox: aligned pair loads
        process_ox<false>(ys + cx + ox, xr + cx + ox, xg + cx + ox, xb + cx + ox,
                          yreg, r0t, aW, aR, aG, aB);
    for (int ox = -5; ox <= 5; ox += 2)    // odd ox: y via shifted copy, x scalar
        process_ox<true>(ysB + cx + ox - 1, xr + cx + ox, xg + cx + ox, xb + cx + ox,
                         yreg, r0t, aW, aR, aG, aB);

    // ---- epilogue: lanes 1..30 own 60 output cols ----
    if (lane >= 1 && lane <= 30) {
        int gc = (colBase + 2 * (lane - 1)) & MASK;   // even, pair contiguous
        float* ob = out + (size_t)n * 3 * PLANE;
        #pragma unroll
        for (int k = 0; k < 4; ++k) {
            float wa, wb, ra, rb, ga, gb, ba, bb;
            up2(aW[k], wa, wb);
            up2(aR[k], ra, rb);
            up2(aG[k], ga, gb);
            up2(aB[k], ba, bb);
            float ia = 1.0f / wa, ib = 1.0f / wb;
            int gr = rowBase + warp * R_OUT + k;
            float* o0 = ob + gr * W_IMG + gc;
            *(float2*)(o0)             = make_float2(fminf(fmaxf(ra * ia, 0.f), 1.f),
                                                     fminf(fmaxf(rb * ib, 0.f), 1.f));
            *(float2*)(o0 + PLANE)     = make_float2(fminf(fmaxf(ga * ia, 0.f), 1.f),
                                                     fminf(fmaxf(gb * ib, 0.f), 1.f));
            *(float2*)(o0 + 2 * PLANE) = make_float2(fminf(fmaxf(ba * ia, 0.f), 1.f),
                                                     fminf(fmaxf(bb * ib, 0.f), 1.f));
        }
    }
}

extern "C" void kernel_launch(void* const* d_in, const int* in_sizes, int n_in,
                              void* d_out, int out_size)
{
    (void)in_sizes; (void)n_in; (void)out_size;
    const float* x = (const float*)d_in[0];
    float* out = (float*)d_out;

    dim3 block(32, WARPS, 1);
    dim3 grid((W_IMG + OUT_COLS - 1) / OUT_COLS,   // 9 (last tile wraps; duplicate
              W_IMG / TILE_ROWS,                   //    writes are bitwise identical)
              2);                                  // 9*32*2 = 576 blocks = one wave
    nlm_kernel<<<grid, block>>>(x, out);
}

// round 5
// speedup vs baseline: 1.0733x; 1.0733x over previous
#include <cuda_runtime.h>

#define MASK  511
#define W_IMG 512
#define PLANE (512 * 512)

#define R_OUT     8                      // out rows per warp
#define WARPS     2
#define TILE_ROWS 16                     // out rows per block
#define OUT_COLS  60                     // out cols per block (lanes 1..30, 2 each)
#define TROWS     30                     // 16 + 2*7 halo
#define TCOLS     76                     // 75 used + 1 pad (even => 8B alignment holds)
#define TPIX      (TROWS * TCOLS)        // 2280
#define FULLM     0xffffffffu

typedef unsigned long long u64;

__device__ __forceinline__ u64 pk(float a, float b) {
    u64 r; asm("mov.b64 %0, {%1, %2};" : "=l"(r) : "f"(a), "f"(b)); return r;
}
__device__ __forceinline__ void up2(u64 v, float& a, float& b) {
    asm("mov.b64 {%0, %1}, %2;" : "=f"(a), "=f"(b) : "l"(v));
}
__device__ __forceinline__ u64 fma2(u64 a, u64 b, u64 c) {
    u64 d; asm("fma.rn.f32x2 %0, %1, %2, %3;" : "=l"(d) : "l"(a), "l"(b), "l"(c)); return d;
}
__device__ __forceinline__ u64 mul2(u64 a, u64 b) {
    u64 d; asm("mul.rn.f32x2 %0, %1, %2;" : "=l"(d) : "l"(a), "l"(b)); return d;
}
__device__ __forceinline__ u64 add2(u64 a, u64 b) {
    u64 d; asm("add.rn.f32x2 %0, %1, %2;" : "=l"(d) : "l"(a), "l"(b)); return d;
}
__device__ __forceinline__ float fsqrt_ap(float x) {
    float r; asm("sqrt.approx.f32 %0, %1;" : "=f"(r) : "f"(x)); return r;
}
__device__ __forceinline__ float fex2(float x) {
    float r; asm("ex2.approx.f32 %0, %1;" : "=f"(r) : "f"(x)); return r;
}

#define NEG1 0xBF800000BF800000ULL               /* {-1.f,-1.f} */
#define KEXP (-0.48089834696298784f)             /* -log2(e)/3  */

// One horizontal offset ox, all 11 oy, R_OUT=8 rows.
// shy   : pair-aligned shifted-y base (plane + column); for odd ox this is the
//         ysB (shift-by-one) plane so the pair load stays aligned.
// x*0   : channel plane + x fetch column (cx+ox for even; cx+ox+1 for odd —
//         even either way => aligned LDS.64).
// ODD   : weights/accumulation target columns (cx+1,cx+2) [phase B] instead of
//         (cx,cx+1) [phase A]; phases are merged by shuffle in the epilogue.
template<bool ODD>
__device__ __forceinline__ void process_ox(
    const float* __restrict__ shy,
    const float* __restrict__ xr0, const float* __restrict__ xg0,
    const float* __restrict__ xb0,
    const u64* __restrict__ yreg, int r0t,
    u64* aW, u64* aR, u64* aG, u64* aB)
{
    // shifted-y pairs, tile rows r0t .. r0t+21, cached across all oy
    u64 ysh[22];
    #pragma unroll
    for (int m = 0; m < 22; ++m) {
        float2 v = *(const float2*)&shy[(r0t + m) * TCOLS];
        ysh[m] = pk(v.x, v.y);
    }

    #pragma unroll
    for (int oyi = 0; oyi < 11; ++oyi) {        // oy = oyi - 5
        u64 s[12];
        #pragma unroll
        for (int j = 0; j < 12; ++j) {
            u64 d = fma2(NEG1, ysh[j + oyi], yreg[j]);   // own - shifted
            s[j]  = mul2(d, d);
        }

        u64 vs = add2(add2(s[0], s[1]), add2(s[2], s[3]));
        const int xrow = (r0t + 2 + oyi) * TCOLS;        // r0t+7+k+oy at k=0

        #pragma unroll
        for (int k = 0; k < 8; ++k) {
            u64 v5 = add2(vs, s[k + 4]);
            if (k < 7) vs = fma2(NEG1, s[k], v5);        // slide window

            float a, b; up2(v5, a, b);
            float t = a + b;
            float d2lo, d2hi;
            if (!ODD) {
                float am = __shfl_up_sync  (FULLM, a, 1);
                float bm = __shfl_up_sync  (FULLM, b, 1);
                float ap = __shfl_down_sync(FULLM, a, 1);
                float bp = __shfl_down_sync(FULLM, b, 1);
                d2lo = ((am + bm) + t) + ap;             // col cx
                d2hi = (bm + t) + (ap + bp);             // col cx+1
            } else {
                float bm = __shfl_up_sync  (FULLM, b, 1);
                float ap = __shfl_down_sync(FULLM, a, 1);
                float bp = __shfl_down_sync(FULLM, b, 1);
                float a2 = __shfl_down_sync(FULLM, a, 2);
                float q  = ap + bp;
                d2lo = (bm + t) + q;                     // col cx+1
                d2hi = (t + q) + a2;                     // col cx+2
            }
            float wlo = fex2(fsqrt_ap(d2lo) * KEXP);
            float whi = fex2(fsqrt_ap(d2hi) * KEXP);
            u64  w2   = pk(wlo, whi);
            aW[k] = add2(aW[k], w2);

            const int xi = xrow + k * TCOLS;
            float2 vr = *(const float2*)&xr0[xi];
            float2 vg = *(const float2*)&xg0[xi];
            float2 vb = *(const float2*)&xb0[xi];
            aR[k] = fma2(w2, pk(vr.x, vr.y), aR[k]);
            aG[k] = fma2(w2, pk(vg.x, vg.y), aG[k]);
            aB[k] = fma2(w2, pk(vb.x, vb.y), aB[k]);
        }
    }
}

__global__ __launch_bounds__(32 * WARPS, 4)
void nlm_kernel(const float* __restrict__ x, float* __restrict__ out)
{
    __shared__ __align__(16) float smem[5 * TPIX];   // ys | ysB | xr | xg | xb
    float* ys  = smem;
    float* ysB = smem + TPIX;                        // ysB[r][c] = ys[r][c+1]
    float* xr  = smem + 2 * TPIX;
    float* xg  = smem + 3 * TPIX;
    float* xb  = smem + 4 * TPIX;

    const int lane = threadIdx.x;
    const int warp = threadIdx.y;
    const int tid  = warp * 32 + lane;

    const int n       = blockIdx.z;
    const int rowBase = blockIdx.y * TILE_ROWS;
    const int colBase = blockIdx.x * OUT_COLS;
    const int rowTop  = rowBase - 7 + 512;
    const int colLeft = colBase - 8 + 512;

    const float* xbase = x + (size_t)n * 3 * PLANE;

    for (int idx = tid; idx < TPIX; idx += 32 * WARPS) {
        int r  = idx / TCOLS;
        int c  = idx - r * TCOLS;
        int gy = (rowTop + r) & MASK;
        int gx = (colLeft + c) & MASK;
        const float* p = xbase + gy * W_IMG + gx;
        float rv = p[0];
        float gv = p[PLANE];
        float bv = p[2 * PLANE];
        float rc = fminf(fmaxf(rv, 0.f), 1.f);
        float gc = fminf(fmaxf(gv, 0.f), 1.f);
        float bc = fminf(fmaxf(bv, 0.f), 1.f);
        float yv = 0.299f * rc + 0.587f * gc + 0.114f * bc;
        xr[idx] = rv; xg[idx] = gv; xb[idx] = bv; ys[idx] = yv;
        if (c) ysB[idx - 1] = yv;
    }
    __syncthreads();

    const int r0t = warp * R_OUT;          // warp's out-row start (tile row +7)
    const int cx  = 6 + 2 * lane;          // own pair: tile cols (cx, cx+1)

    // own pairs, template rows r0t+5 .. r0t+16
    u64 yreg[12];
    #pragma unroll
    for (int j = 0; j < 12; ++j) {
        float2 v = *(const float2*)&ys[(r0t + 5 + j) * TCOLS + cx];
        yreg[j] = pk(v.x, v.y);
    }

    u64 aWA[8], aRA[8], aGA[8], aBA[8];    // phase A: cols (cx, cx+1)
    u64 aWB[8], aRB[8], aGB[8], aBB[8];    // phase B: cols (cx+1, cx+2)
    #pragma unroll
    for (int k = 0; k < 8; ++k) {
        aWA[k] = 0ULL; aRA[k] = 0ULL; aGA[k] = 0ULL; aBA[k] = 0ULL;
        aWB[k] = 0ULL; aRB[k] = 0ULL; aGB[k] = 0ULL; aBB[k] = 0ULL;
    }

    #pragma unroll 1
    for (int ox = -4; ox <= 4; ox += 2)    // even offsets -> phase A
        process_ox<false>(ys + cx + ox,
                          xr + cx + ox, xg + cx + ox, xb + cx + ox,
                          yreg, r0t, aWA, aRA, aGA, aBA);
    #pragma unroll 1
    for (int ox = -5; ox <= 5; ox += 2)    // odd offsets -> phase B
        process_ox<true>(ysB + cx + ox - 1,
                         xr + cx + ox + 1, xg + cx + ox + 1, xb + cx + ox + 1,
                         yreg, r0t, aWB, aRB, aGB, aBB);

    // ---- merge phases and write (lanes 1..30 own 60 output cols) ----
    float* ob = out + (size_t)n * 3 * PLANE;
    const int gc = (colBase + 2 * (lane - 1)) & MASK;   // even; pair contiguous
    const bool wr = (lane >= 1 && lane <= 30);

    #pragma unroll
    for (int k = 0; k < 8; ++k) {
        float wa0, wa1, wb0, wb1, ra0, ra1, rb0, rb1;
        float ga0, ga1, gb0, gb1, ba0, ba1, bb0, bb1;
        up2(aWA[k], wa0, wa1); up2(aWB[k], wb0, wb1);
        up2(aRA[k], ra0, ra1); up2(aRB[k], rb0, rb1);
        up2(aGA[k], ga0, ga1); up2(aGB[k], gb0, gb1);
        up2(aBA[k], ba0, ba1); up2(aBB[k], bb0, bb1);
        // lane L's lo column (cx) takes lane L-1's phase-B hi (col cx)
        float wph = __shfl_up_sync(FULLM, wb1, 1);
        float rph = __shfl_up_sync(FULLM, rb1, 1);
        float gph = __shfl_up_sync(FULLM, gb1, 1);
        float bph = __shfl_up_sync(FULLM, bb1, 1);
        float wlo = wa0 + wph, whi = wa1 + wb0;
        float rlo = ra0 + rph, rhi = ra1 + rb0;
        float glo = ga0 + gph, ghi = ga1 + gb0;
        float blo = ba0 + bph, bhi = ba1 + bb0;
        if (wr) {
            float il = 1.0f / wlo, ih = 1.0f / whi;
            int gr = rowBase + r0t + k;
            float* o0 = ob + gr * W_IMG + gc;
            *(float2*)(o0)             = make_float2(fminf(fmaxf(rlo * il, 0.f), 1.f),
                                                     fminf(fmaxf(rhi * ih, 0.f), 1.f));
            *(float2*)(o0 + PLANE)     = make_float2(fminf(fmaxf(glo * il, 0.f), 1.f),
                                                     fminf(fmaxf(ghi * ih, 0.f), 1.f));
            *(float2*)(o0 + 2 * PLANE) = make_float2(fminf(fmaxf(blo * il, 0.f), 1.f),
                                                     fminf(fmaxf(bhi * ih, 0.f), 1.f));
        }
    }
}

extern "C" void kernel_launch(void* const* d_in, const int* in_sizes, int n_in,
                              void* d_out, int out_size)
{
    (void)in_sizes; (void)n_in; (void)out_size;
    const float* x = (const float*)d_in[0];
    float* out = (float*)d_out;

    dim3 block(32, WARPS, 1);
    dim3 grid((W_IMG + OUT_COLS - 1) / OUT_COLS,   // 9 (last tile wraps; duplicate
              W_IMG / TILE_ROWS,                   //    writes are bitwise identical)
              2);                                  // 9*32*2 = 576 = one wave @4/SM
    nlm_kernel<<<grid, block>>>(x, out);
}

// round 6
// speedup vs baseline: 1.1376x; 1.0599x over previous
#include <cuda_runtime.h>

#define MASK  511
#define W_IMG 512
#define PLANE (512 * 512)

#define R_OUT     4                      // out rows per warp
#define WARPS     4
#define TILE_ROWS 16                     // out rows per block
#define OUT_COLS  60                     // out cols per block (lanes 1..30, 2 each)
#define TROWS     30                     // 16 + 2*7 halo
#define TCOLS     76                     // 75 used + 1 pad (even => 8B alignment holds)
#define TPIX      (TROWS * TCOLS)        // 2280
#define FULLM     0xffffffffu

typedef unsigned long long u64;

__device__ __forceinline__ u64 pk(float a, float b) {
    u64 r; asm("mov.b64 %0, {%1, %2};" : "=l"(r) : "f"(a), "f"(b)); return r;
}
__device__ __forceinline__ void up2(u64 v, float& a, float& b) {
    asm("mov.b64 {%0, %1}, %2;" : "=f"(a), "=f"(b) : "l"(v));
}
__device__ __forceinline__ u64 fma2(u64 a, u64 b, u64 c) {
    u64 d; asm("fma.rn.f32x2 %0, %1, %2, %3;" : "=l"(d) : "l"(a), "l"(b), "l"(c)); return d;
}
__device__ __forceinline__ u64 mul2(u64 a, u64 b) {
    u64 d; asm("mul.rn.f32x2 %0, %1, %2;" : "=l"(d) : "l"(a), "l"(b)); return d;
}
__device__ __forceinline__ u64 add2(u64 a, u64 b) {
    u64 d; asm("add.rn.f32x2 %0, %1, %2;" : "=l"(d) : "l"(a), "l"(b)); return d;
}
__device__ __forceinline__ float fsqrt_ap(float x) {
    float r; asm("sqrt.approx.f32 %0, %1;" : "=f"(r) : "f"(x)); return r;
}
__device__ __forceinline__ float fex2(float x) {
    float r; asm("ex2.approx.f32 %0, %1;" : "=f"(r) : "f"(x)); return r;
}

#define NEG1 0xBF800000BF800000ULL               /* {-1.f,-1.f} */
#define KEXP (-0.48089834696298784f)             /* -log2(e)/3  */

// One horizontal offset ox, all 11 oy, R_OUT=4 rows.
// shy : pair-aligned shifted-y base (for odd ox it's the ysB shift-by-1 plane).
// x*0 : channel plane + x fetch column (even either parity => aligned LDS.64).
// ODD : weights/accumulation target cols (cx+1,cx+2) [phase B] vs (cx,cx+1) [A].
template<bool ODD>
__device__ __forceinline__ void process_ox(
    const float* __restrict__ shy,
    const float* __restrict__ xr0, const float* __restrict__ xg0,
    const float* __restrict__ xb0,
    const u64* __restrict__ yreg, int r0t,
    u64* aW, u64* aR, u64* aG, u64* aB)
{
    // shifted-y pairs, tile rows r0t .. r0t+17, cached across all oy
    u64 ysh[18];
    #pragma unroll
    for (int m = 0; m < 18; ++m) {
        float2 v = *(const float2*)&shy[(r0t + m) * TCOLS];
        ysh[m] = pk(v.x, v.y);
    }

    #pragma unroll
    for (int oyi = 0; oyi < 11; ++oyi) {        // oy = oyi - 5
        u64 s[8];
        #pragma unroll
        for (int j = 0; j < 8; ++j) {
            u64 d = fma2(NEG1, ysh[j + oyi], yreg[j]);   // own - shifted
            s[j]  = mul2(d, d);
        }

        u64 vs = add2(add2(s[0], s[1]), add2(s[2], s[3]));
        const int xrow = (r0t + 2 + oyi) * TCOLS;        // r0t+7+k+oy at k=0

        #pragma unroll
        for (int k = 0; k < 4; ++k) {
            u64 v5 = add2(vs, s[k + 4]);
            if (k < 3) vs = fma2(NEG1, s[k], v5);        // slide window

            float a, b; up2(v5, a, b);
            float t = a + b;
            float d2lo, d2hi;
            if (!ODD) {
                float am = __shfl_up_sync  (FULLM, a, 1);
                float bm = __shfl_up_sync  (FULLM, b, 1);
                float ap = __shfl_down_sync(FULLM, a, 1);
                float bp = __shfl_down_sync(FULLM, b, 1);
                d2lo = ((am + bm) + t) + ap;             // col cx
                d2hi = (bm + t) + (ap + bp);             // col cx+1
            } else {
                float bm = __shfl_up_sync  (FULLM, b, 1);
                float ap = __shfl_down_sync(FULLM, a, 1);
                float bp = __shfl_down_sync(FULLM, b, 1);
                float a2 = __shfl_down_sync(FULLM, a, 2);
                float q  = ap + bp;
                d2lo = (bm + t) + q;                     // col cx+1
                d2hi = (t + q) + a2;                     // col cx+2 (no up-shfl)
            }
            float wlo = fex2(fsqrt_ap(d2lo) * KEXP);
            float whi = fex2(fsqrt_ap(d2hi) * KEXP);
            u64  w2   = pk(wlo, whi);
            aW[k] = add2(aW[k], w2);

            const int xi = xrow + k * TCOLS;
            float2 vr = *(const float2*)&xr0[xi];
            float2 vg = *(const float2*)&xg0[xi];
            float2 vb = *(const float2*)&xb0[xi];
            aR[k] = fma2(w2, pk(vr.x, vr.y), aR[k]);
            aG[k] = fma2(w2, pk(vg.x, vg.y), aG[k]);
            aB[k] = fma2(w2, pk(vb.x, vb.y), aB[k]);
        }
    }
}

__global__ __launch_bounds__(32 * WARPS, 4)
void nlm_kernel(const float* __restrict__ x, float* __restrict__ out)
{
    __shared__ __align__(16) float smem[5 * TPIX];   // ys | ysB | xr | xg | xb
    float* ys  = smem;
    float* ysB = smem + TPIX;                        // ysB[r][c] = ys[r][c+1]
    float* xr  = smem + 2 * TPIX;
    float* xg  = smem + 3 * TPIX;
    float* xb  = smem + 4 * TPIX;

    const int lane = threadIdx.x;
    const int warp = threadIdx.y;
    const int tid  = warp * 32 + lane;

    const int n       = blockIdx.z;
    const int rowBase = blockIdx.y * TILE_ROWS;
    const int colBase = blockIdx.x * OUT_COLS;
    const int rowTop  = rowBase - 7 + 512;
    const int colLeft = colBase - 8 + 512;

    const float* xbase = x + (size_t)n * 3 * PLANE;

    for (int idx = tid; idx < TPIX; idx += 32 * WARPS) {
        int r  = idx / TCOLS;
        int c  = idx - r * TCOLS;
        int gy = (rowTop + r) & MASK;
        int gx = (colLeft + c) & MASK;
        const float* p = xbase + gy * W_IMG + gx;
        float rv = p[0];
        float gv = p[PLANE];
        float bv = p[2 * PLANE];
        float rc = fminf(fmaxf(rv, 0.f), 1.f);
        float gc = fminf(fmaxf(gv, 0.f), 1.f);
        float bc = fminf(fmaxf(bv, 0.f), 1.f);
        float yv = 0.299f * rc + 0.587f * gc + 0.114f * bc;
        xr[idx] = rv; xg[idx] = gv; xb[idx] = bv; ys[idx] = yv;
        if (c) ysB[idx - 1] = yv;
    }
    __syncthreads();

    const int r0t = warp * R_OUT;          // warp's out-row start (tile row +7)
    const int cx  = 6 + 2 * lane;          // own pair: tile cols (cx, cx+1)

    // own pairs, template rows r0t+5 .. r0t+12
    u64 yreg[8];
    #pragma unroll
    for (int j = 0; j < 8; ++j) {
        float2 v = *(const float2*)&ys[(r0t + 5 + j) * TCOLS + cx];
        yreg[j] = pk(v.x, v.y);
    }

    u64 aW[4], aR[4], aG[4], aB[4];        // single set; starts in phase-B layout
    #pragma unroll
    for (int k = 0; k < 4; ++k) { aW[k] = 0ULL; aR[k] = 0ULL; aG[k] = 0ULL; aB[k] = 0ULL; }

    // ---- odd offsets first, phase-B layout: cols (cx+1, cx+2) ----
    #pragma unroll 1
    for (int ox = -5; ox <= 5; ox += 2)
        process_ox<true>(ysB + cx + ox - 1,
                         xr + cx + ox + 1, xg + cx + ox + 1, xb + cx + ox + 1,
                         yreg, r0t, aW, aR, aG, aB);

    // ---- re-align phase B -> phase A: lane L's lo(cx) = lane L-1's hi ----
    #pragma unroll
    for (int k = 0; k < 4; ++k) {
        float lo, hi;
        up2(aW[k], lo, hi); aW[k] = pk(__shfl_up_sync(FULLM, hi, 1), lo);
        up2(aR[k], lo, hi); aR[k] = pk(__shfl_up_sync(FULLM, hi, 1), lo);
        up2(aG[k], lo, hi); aG[k] = pk(__shfl_up_sync(FULLM, hi, 1), lo);
        up2(aB[k], lo, hi); aB[k] = pk(__shfl_up_sync(FULLM, hi, 1), lo);
    }

    // ---- even offsets, phase-A layout: cols (cx, cx+1) ----
    #pragma unroll 1
    for (int ox = -4; ox <= 4; ox += 2)
        process_ox<false>(ys + cx + ox,
                          xr + cx + ox, xg + cx + ox, xb + cx + ox,
                          yreg, r0t, aW, aR, aG, aB);

    // ---- write output (lanes 1..30 own 60 output cols) ----
    if (lane >= 1 && lane <= 30) {
        int gc = (colBase + 2 * (lane - 1)) & MASK;   // even; pair contiguous
        float* ob = out + (size_t)n * 3 * PLANE;
        #pragma unroll
        for (int k = 0; k < 4; ++k) {
            float wlo, whi, rlo, rhi, glo, ghi, blo, bhi;
            up2(aW[k], wlo, whi);
            up2(aR[k], rlo, rhi);
            up2(aG[k], glo, ghi);
            up2(aB[k], blo, bhi);
            float il = 1.0f / wlo, ih = 1.0f / whi;
            int gr = rowBase + r0t + k;
            float* o0 = ob + gr * W_IMG + gc;
            *(float2*)(o0)             = make_float2(fminf(fmaxf(rlo * il, 0.f), 1.f),
                                                     fminf(fmaxf(rhi * ih, 0.f), 1.f));
            *(float2*)(o0 + PLANE)     = make_float2(fminf(fmaxf(glo * il, 0.f), 1.f),
                                                     fminf(fmaxf(ghi * ih, 0.f), 1.f));
            *(float2*)(o0 + 2 * PLANE) = make_float2(fminf(fmaxf(blo * il, 0.f), 1.f),
                                                     fminf(fmaxf(bhi * ih, 0.f), 1.f));
        }
    }
}

extern "C" void kernel_launch(void* const* d_in, const int* in_sizes, int n_in,
                              void* d_out, int out_size)
{
    (void)in_sizes; (void)n_in; (void)out_size;
    const float* x = (const float*)d_in[0];
    float* out = (float*)d_out;

    dim3 block(32, WARPS, 1);
    dim3 grid((W_IMG + OUT_COLS - 1) / OUT_COLS,   // 9 (last tile wraps; duplicate
              W_IMG / TILE_ROWS,                   //    writes are bitwise identical)
              2);                                  // 9*32*2 = 576 = one wave @4/SM
    nlm_kernel<<<grid, block>>>(x, out);
}

// round 7
// speedup vs baseline: 1.2000x; 1.0548x over previous
#include <cuda_runtime.h>

#define MASK  511
#define W_IMG 512
#define PLANE (512 * 512)

#define R_OUT     4                      // out rows per warp
#define WARPS     4
#define TILE_ROWS 16                     // out rows per block
#define OUT_COLS  60                     // out cols per block (lanes 1..30, 2 each)
#define TROWS     30                     // 16 + 2*7 halo
#define TCOLS     76                     // 75 used + 1 pad (even => 8B alignment holds)
#define TPIX      (TROWS * TCOLS)        // 2280
#define FULLM     0xffffffffu

typedef unsigned long long u64;

__device__ __forceinline__ u64 pk(float a, float b) {
    u64 r; asm("mov.b64 %0, {%1, %2};" : "=l"(r) : "f"(a), "f"(b)); return r;
}
__device__ __forceinline__ void up2(u64 v, float& a, float& b) {
    asm("mov.b64 {%0, %1}, %2;" : "=f"(a), "=f"(b) : "l"(v));
}
__device__ __forceinline__ u64 fma2(u64 a, u64 b, u64 c) {
    u64 d; asm("fma.rn.f32x2 %0, %1, %2, %3;" : "=l"(d) : "l"(a), "l"(b), "l"(c)); return d;
}
__device__ __forceinline__ u64 mul2(u64 a, u64 b) {
    u64 d; asm("mul.rn.f32x2 %0, %1, %2;" : "=l"(d) : "l"(a), "l"(b)); return d;
}
__device__ __forceinline__ u64 add2(u64 a, u64 b) {
    u64 d; asm("add.rn.f32x2 %0, %1, %2;" : "=l"(d) : "l"(a), "l"(b)); return d;
}
__device__ __forceinline__ float fsqrt_ap(float x) {
    float r; asm("sqrt.approx.f32 %0, %1;" : "=f"(r) : "f"(x)); return r;
}
// ex2 of the NEGATED input; ptxas folds the neg into the MUFU operand modifier
__device__ __forceinline__ float fex2n(float x) {
    float r; asm("ex2.approx.f32 %0, %1;" : "=f"(r) : "f"(-x)); return r;
}

#define NEG1 0xBF800000BF800000ULL               /* {-1.f,-1.f} */
#define YSCL 0.4808983469629878f                 /* log2(e)/3: pre-folded into y */

// One horizontal offset ox, all 11 oy, R_OUT=4 rows.
// shy : pair-aligned shifted-y base (for odd ox it's the ysB shift-by-1 plane).
// x*0 : channel plane + x fetch column (even either parity => aligned LDS.64).
// ODD : accumulation targets cols (cx+1,cx+2) [phase B] vs (cx,cx+1) [phase A].
template<bool ODD>
__device__ __forceinline__ void process_ox(
    const float* __restrict__ shy,
    const float* __restrict__ xr0, const float* __restrict__ xg0,
    const float* __restrict__ xb0,
    const u64* __restrict__ yreg, int r0t,
    u64* aW, u64* aR, u64* aG, u64* aB)
{
    // shifted-y pairs (pre-scaled), tile rows r0t .. r0t+17, cached across all oy
    u64 ysh[18];
    #pragma unroll
    for (int m = 0; m < 18; ++m)
        ysh[m] = *(const u64*)&shy[(r0t + m) * TCOLS];

    #pragma unroll
    for (int oyi = 0; oyi < 11; ++oyi) {        // oy = oyi - 5
        u64 s[8];
        #pragma unroll
        for (int j = 0; j < 8; ++j) {
            u64 d = fma2(NEG1, ysh[j + oyi], yreg[j]);   // own - shifted (scaled)
            s[j]  = mul2(d, d);
        }

        u64 vs = add2(add2(s[0], s[1]), add2(s[2], s[3]));
        const float* xrr = xr0 + (r0t + 2 + oyi) * TCOLS;  // row r0t+7+k+oy @k=0
        const float* xgr = xg0 + (r0t + 2 + oyi) * TCOLS;
        const float* xbr = xb0 + (r0t + 2 + oyi) * TCOLS;

        #pragma unroll
        for (int k = 0; k < 4; ++k) {
            u64 v5 = add2(vs, s[k + 4]);
            if (k < 3) vs = fma2(NEG1, s[k], v5);        // slide window

            float a, b; up2(v5, a, b);
            float t = a + b;                             // local pair sum
            float d2lo, d2hi;
            if (!ODD) {
                float cm = __shfl_up_sync  (FULLM, t, 1);  // a-1 + b-1
                float cp = __shfl_down_sync(FULLM, t, 1);  // a+1 + b+1
                float ap = __shfl_down_sync(FULLM, a, 1);
                float bm = __shfl_up_sync  (FULLM, b, 1);
                d2lo = (cm + t) + ap;                    // col cx
                d2hi = (bm + t) + cp;                    // col cx+1
            } else {
                float cp = __shfl_down_sync(FULLM, t, 1);  // a+1 + b+1
                float bm = __shfl_up_sync  (FULLM, b, 1);
                float a2 = __shfl_down_sync(FULLM, a, 2);
                d2lo = (bm + t) + cp;                    // col cx+1
                d2hi = (t + cp) + a2;                    // col cx+2
            }
            float wlo = fex2n(fsqrt_ap(d2lo));           // 2^(-scl*dist) = e^(-dist/3)
            float whi = fex2n(fsqrt_ap(d2hi));
            u64  w2   = pk(wlo, whi);
            aW[k] = add2(aW[k], w2);
            aR[k] = fma2(w2, *(const u64*)&xrr[k * TCOLS], aR[k]);
            aG[k] = fma2(w2, *(const u64*)&xgr[k * TCOLS], aG[k]);
            aB[k] = fma2(w2, *(const u64*)&xbr[k * TCOLS], aB[k]);
        }
    }
}

__global__ __launch_bounds__(32 * WARPS, 4)
void nlm_kernel(const float* __restrict__ x, float* __restrict__ out)
{
    __shared__ __align__(16) float smem[5 * TPIX];   // ys | ysB | xr | xg | xb
    float* ys  = smem;
    float* ysB = smem + TPIX;                        // ysB[r][c] = ys[r][c+1]
    float* xr  = smem + 2 * TPIX;
    float* xg  = smem + 3 * TPIX;
    float* xb  = smem + 4 * TPIX;

    const int lane = threadIdx.x;
    const int warp = threadIdx.y;
    const int tid  = warp * 32 + lane;

    const int n       = blockIdx.z;
    const int rowBase = blockIdx.y * TILE_ROWS;
    const int colBase = blockIdx.x * OUT_COLS;
    const int rowTop  = rowBase - 7 + 512;
    const int colLeft = colBase - 8 + 512;

    const float* xbase = x + (size_t)n * 3 * PLANE;

    for (int idx = tid; idx < TPIX; idx += 32 * WARPS) {
        int r  = idx / TCOLS;
        int c  = idx - r * TCOLS;
        int gy = (rowTop + r) & MASK;
        int gx = (colLeft + c) & MASK;
        const float* p = xbase + gy * W_IMG + gx;
        float rv = p[0];
        float gv = p[PLANE];
        float bv = p[2 * PLANE];
        float rc = fminf(fmaxf(rv, 0.f), 1.f);
        float gc = fminf(fmaxf(gv, 0.f), 1.f);
        float bc = fminf(fmaxf(bv, 0.f), 1.f);
        // luminance pre-scaled by log2(e)/3 so the weight is ex2(-sqrt(d2))
        float yv = (0.299f * YSCL) * rc + (0.587f * YSCL) * gc + (0.114f * YSCL) * bc;
        xr[idx] = rv; xg[idx] = gv; xb[idx] = bv; ys[idx] = yv;
        if (c) ysB[idx - 1] = yv;
    }
    __syncthreads();

    const int r0t = warp * R_OUT;          // warp's out-row start (tile row +7)
    const int cx  = 6 + 2 * lane;          // own pair: tile cols (cx, cx+1)

    // own pairs (scaled), template rows r0t+5 .. r0t+12
    u64 yreg[8];
    #pragma unroll
    for (int j = 0; j < 8; ++j)
        yreg[j] = *(const u64*)&ys[(r0t + 5 + j) * TCOLS + cx];

    u64 aW[4], aR[4], aG[4], aB[4];        // single set; starts in phase-B layout
    #pragma unroll
    for (int k = 0; k < 4; ++k) { aW[k] = 0ULL; aR[k] = 0ULL; aG[k] = 0ULL; aB[k] = 0ULL; }

    // ---- odd offsets first, phase-B layout: cols (cx+1, cx+2) ----
    #pragma unroll 1
    for (int ox = -5; ox <= 5; ox += 2)
        process_ox<true>(ysB + cx + ox - 1,
                         xr + cx + ox + 1, xg + cx + ox + 1, xb + cx + ox + 1,
                         yreg, r0t, aW, aR, aG, aB);

    // ---- re-align phase B -> phase A: lane L's lo(cx) = lane L-1's hi ----
    #pragma unroll
    for (int k = 0; k < 4; ++k) {
        float lo, hi;
        up2(aW[k], lo, hi); aW[k] = pk(__shfl_up_sync(FULLM, hi, 1), lo);
        up2(aR[k], lo, hi); aR[k] = pk(__shfl_up_sync(FULLM, hi, 1), lo);
        up2(aG[k], lo, hi); aG[k] = pk(__shfl_up_sync(FULLM, hi, 1), lo);
        up2(aB[k], lo, hi); aB[k] = pk(__shfl_up_sync(FULLM, hi, 1), lo);
    }

    // ---- even offsets, phase-A layout: cols (cx, cx+1) ----
    #pragma unroll 1
    for (int ox = -4; ox <= 4; ox += 2)
        process_ox<false>(ys + cx + ox,
                          xr + cx + ox, xg + cx + ox, xb + cx + ox,
                          yreg, r0t, aW, aR, aG, aB);

    // ---- write output (lanes 1..30 own 60 output cols) ----
    if (lane >= 1 && lane <= 30) {
        int gc = (colBase + 2 * (lane - 1)) & MASK;   // even; pair contiguous
        float* ob = out + (size_t)n * 3 * PLANE;
        #pragma unroll
        for (int k = 0; k < 4; ++k) {
            float wlo, whi, rlo, rhi, glo, ghi, blo, bhi;
            up2(aW[k], wlo, whi);
            up2(aR[k], rlo, rhi);
            up2(aG[k], glo, ghi);
            up2(aB[k], blo, bhi);
            float il = 1.0f / wlo, ih = 1.0f / whi;
            int gr = rowBase + r0t + k;
            float* o0 = ob + gr * W_IMG + gc;
            *(float2*)(o0)             = make_float2(fminf(fmaxf(rlo * il, 0.f), 1.f),
                                                     fminf(fmaxf(rhi * ih, 0.f), 1.f));
            *(float2*)(o0 + PLANE)     = make_float2(fminf(fmaxf(glo * il, 0.f), 1.f),
                                                     fminf(fmaxf(ghi * ih, 0.f), 1.f));
            *(float2*)(o0 + 2 * PLANE) = make_float2(fminf(fmaxf(blo * il, 0.f), 1.f),
                                                     fminf(fmaxf(bhi * ih, 0.f), 1.f));
        }
    }
}

extern "C" void kernel_launch(void* const* d_in, const int* in_sizes, int n_in,
                              void* d_out, int out_size)
{
    (void)in_sizes; (void)n_in; (void)out_size;
    const float* x = (const float*)d_in[0];
    float* out = (float*)d_out;

    dim3 block(32, WARPS, 1);
    dim3 grid((W_IMG + OUT_COLS - 1) / OUT_COLS,   // 9 (last tile wraps; duplicate
              W_IMG / TILE_ROWS,                   //    writes are bitwise identical)
              2);                                  // 9*32*2 = 576 = one wave @4/SM
    nlm_kernel<<<grid, block>>>(x, out);
}

// round 8
// speedup vs baseline: 1.2150x; 1.0125x over previous
#include <cuda_runtime.h>

#define MASK  511
#define W_IMG 512
#define PLANE (512 * 512)

#define R_OUT     4                      // out rows per warp
#define WARPS     4
#define TILE_ROWS 16                     // out rows per block
#define OUT_COLS  60                     // out cols per block (lanes 1..30, 2 each)
#define TROWS     30                     // 16 + 2*7 halo
#define TCOLS     76                     // 75 used + 1 pad (even => 8B alignment holds)
#define TPIX      (TROWS * TCOLS)        // 2280
#define FULLM     0xffffffffu

typedef unsigned long long u64;

__device__ __forceinline__ u64 pk(float a, float b) {
    u64 r; asm("mov.b64 %0, {%1, %2};" : "=l"(r) : "f"(a), "f"(b)); return r;
}
__device__ __forceinline__ void up2(u64 v, float& a, float& b) {
    asm("mov.b64 {%0, %1}, %2;" : "=f"(a), "=f"(b) : "l"(v));
}
__device__ __forceinline__ u64 fma2(u64 a, u64 b, u64 c) {
    u64 d; asm("fma.rn.f32x2 %0, %1, %2, %3;" : "=l"(d) : "l"(a), "l"(b), "l"(c)); return d;
}
__device__ __forceinline__ u64 mul2(u64 a, u64 b) {
    u64 d; asm("mul.rn.f32x2 %0, %1, %2;" : "=l"(d) : "l"(a), "l"(b)); return d;
}
__device__ __forceinline__ u64 add2(u64 a, u64 b) {
    u64 d; asm("add.rn.f32x2 %0, %1, %2;" : "=l"(d) : "l"(a), "l"(b)); return d;
}
__device__ __forceinline__ float fsqrt_ap(float x) {
    float r; asm("sqrt.approx.f32 %0, %1;" : "=f"(r) : "f"(x)); return r;
}
// ex2 of the NEGATED input; ptxas folds the neg into the MUFU operand modifier
__device__ __forceinline__ float fex2n(float x) {
    float r; asm("ex2.approx.f32 %0, %1;" : "=f"(r) : "f"(-x)); return r;
}

#define NEG1 0xBF800000BF800000ULL               /* {-1.f,-1.f} */
#define YSCL 0.4808983469629878f                 /* log2(e)/3: pre-folded into y */

// One horizontal offset ox, all 11 oy, R_OUT=4 rows.
// shy : pair-aligned shifted-y base (for odd ox it's the ysB shift-by-1 plane).
// x*0 : channel plane + x fetch column (even either parity => aligned LDS.64).
// ODD : accumulation targets cols (cx+1,cx+2) [phase B] vs (cx,cx+1) [phase A].
template<bool ODD>
__device__ __forceinline__ void process_ox(
    const float* __restrict__ shy,
    const float* __restrict__ xr0, const float* __restrict__ xg0,
    const float* __restrict__ xb0,
    const u64* __restrict__ yreg, int r0t,
    u64* aW, u64* aR, u64* aG, u64* aB)
{
    // shifted-y pairs (pre-scaled), tile rows r0t .. r0t+17, cached across all oy
    u64 ysh[18];
    #pragma unroll
    for (int m = 0; m < 18; ++m)
        ysh[m] = *(const u64*)&shy[(r0t + m) * TCOLS];

    #pragma unroll
    for (int oyi = 0; oyi < 11; ++oyi) {        // oy = oyi - 5
        u64 s[8];
        #pragma unroll
        for (int j = 0; j < 8; ++j) {
            u64 d = fma2(NEG1, ysh[j + oyi], yreg[j]);   // own - shifted (scaled)
            s[j]  = mul2(d, d);
        }

        u64 vs = add2(add2(s[0], s[1]), add2(s[2], s[3]));
        const float* xrr = xr0 + (r0t + 2 + oyi) * TCOLS;  // row r0t+7+k+oy @k=0
        const float* xgr = xg0 + (r0t + 2 + oyi) * TCOLS;
        const float* xbr = xb0 + (r0t + 2 + oyi) * TCOLS;

        #pragma unroll
        for (int k = 0; k < 4; ++k) {
            u64 v5 = add2(vs, s[k + 4]);
            if (k < 3) vs = fma2(NEG1, s[k], v5);        // slide window

            float a, b; up2(v5, a, b);
            float t = a + b;                             // local pair sum
            float d2lo, d2hi;
            if (!ODD) {
                float cm = __shfl_up_sync  (FULLM, t, 1);  // a-1 + b-1
                float cp = __shfl_down_sync(FULLM, t, 1);  // a+1 + b+1
                float ap = __shfl_down_sync(FULLM, a, 1);
                float bm = __shfl_up_sync  (FULLM, b, 1);
                d2lo = (cm + t) + ap;                    // col cx
                d2hi = (bm + t) + cp;                    // col cx+1
            } else {
                float cp = __shfl_down_sync(FULLM, t, 1);  // a+1 + b+1
                float bm = __shfl_up_sync  (FULLM, b, 1);
                float a2 = __shfl_down_sync(FULLM, a, 2);
                d2lo = (bm + t) + cp;                    // col cx+1
                d2hi = (t + cp) + a2;                    // col cx+2
            }
            float wlo = fex2n(fsqrt_ap(d2lo));           // 2^(-scl*dist) = e^(-dist/3)
            float whi = fex2n(fsqrt_ap(d2hi));
            u64  w2   = pk(wlo, whi);
            aW[k] = add2(aW[k], w2);
            aR[k] = fma2(w2, *(const u64*)&xrr[k * TCOLS], aR[k]);
            aG[k] = fma2(w2, *(const u64*)&xgr[k * TCOLS], aG[k]);
            aB[k] = fma2(w2, *(const u64*)&xbr[k * TCOLS], aB[k]);
        }
    }
}

__global__ __launch_bounds__(32 * WARPS, 4)
void nlm_kernel(const float* __restrict__ x, float* __restrict__ out)
{
    __shared__ __align__(16) float smem[5 * TPIX];   // ys | ysB | xr | xg | xb
    float* ys  = smem;
    float* ysB = smem + TPIX;                        // ysB[r][c] = ys[r][c+1]
    float* xr  = smem + 2 * TPIX;
    float* xg  = smem + 3 * TPIX;
    float* xb  = smem + 4 * TPIX;

    const int lane = threadIdx.x;
    const int warp = threadIdx.y;
    const int tid  = warp * 32 + lane;

    const int n       = blockIdx.z;
    const int rowBase = blockIdx.y * TILE_ROWS;
    const int colBase = blockIdx.x * OUT_COLS;
    const int rowTop  = rowBase - 7 + 512;
    const int colLeft = colBase - 8 + 512;

    const float* xbase = x + (size_t)n * 3 * PLANE;

    for (int idx = tid; idx < TPIX; idx += 32 * WARPS) {
        int r  = idx / TCOLS;
        int c  = idx - r * TCOLS;
        int gy = (rowTop + r) & MASK;
        int gx = (colLeft + c) & MASK;
        const float* p = xbase + gy * W_IMG + gx;
        float rv = p[0];
        float gv = p[PLANE];
        float bv = p[2 * PLANE];
        float rc = fminf(fmaxf(rv, 0.f), 1.f);
        float gc = fminf(fmaxf(gv, 0.f), 1.f);
        float bc = fminf(fmaxf(bv, 0.f), 1.f);
        // luminance pre-scaled by log2(e)/3 so the weight is ex2(-sqrt(d2))
        float yv = (0.299f * YSCL) * rc + (0.587f * YSCL) * gc + (0.114f * YSCL) * bc;
        xr[idx] = rv; xg[idx] = gv; xb[idx] = bv; ys[idx] = yv;
        if (c) ysB[idx - 1] = yv;
    }
    __syncthreads();

    const int r0t = warp * R_OUT;          // warp's out-row start (tile row +7)
    const int cx  = 6 + 2 * lane;          // own pair: tile cols (cx, cx+1)

    // own pairs (scaled), template rows r0t+5 .. r0t+12
    u64 yreg[8];
    #pragma unroll
    for (int j = 0; j < 8; ++j)
        yreg[j] = *(const u64*)&ys[(r0t + 5 + j) * TCOLS + cx];

    u64 aW[4], aR[4], aG[4], aB[4];        // single set; starts in phase-B layout
    #pragma unroll
    for (int k = 0; k < 4; ++k) { aW[k] = 0ULL; aR[k] = 0ULL; aG[k] = 0ULL; aB[k] = 0ULL; }

    // ---- odd offsets first, phase-B layout: cols (cx+1, cx+2) ----
    #pragma unroll 1
    for (int ox = -5; ox <= 5; ox += 2)
        process_ox<true>(ysB + cx + ox - 1,
                         xr + cx + ox + 1, xg + cx + ox + 1, xb + cx + ox + 1,
                         yreg, r0t, aW, aR, aG, aB);

    // ---- re-align phase B -> phase A: lane L's lo(cx) = lane L-1's hi ----
    #pragma unroll
    for (int k = 0; k < 4; ++k) {
        float lo, hi;
        up2(aW[k], lo, hi); aW[k] = pk(__shfl_up_sync(FULLM, hi, 1), lo);
        up2(aR[k], lo, hi); aR[k] = pk(__shfl_up_sync(FULLM, hi, 1), lo);
        up2(aG[k], lo, hi); aG[k] = pk(__shfl_up_sync(FULLM, hi, 1), lo);
        up2(aB[k], lo, hi); aB[k] = pk(__shfl_up_sync(FULLM, hi, 1), lo);
    }

    // ---- even offsets, phase-A layout: cols (cx, cx+1) ----
    #pragma unroll 1
    for (int ox = -4; ox <= 4; ox += 2)
        process_ox<false>(ys + cx + ox,
                          xr + cx + ox, xg + cx + ox, xb + cx + ox,
                          yreg, r0t, aW, aR, aG, aB);

    // ---- write output (lanes 1..30 own 60 output cols) ----
    if (lane >= 1 && lane <= 30) {
        int gc = (colBase + 2 * (lane - 1)) & MASK;   // even; pair contiguous
        float* ob = out + (size_t)n * 3 * PLANE;
        #pragma unroll
        for (int k = 0; k < 4; ++k) {
            float wlo, whi, rlo, rhi, glo, ghi, blo, bhi;
            up2(aW[k], wlo, whi);
            up2(aR[k], rlo, rhi);
            up2(aG[k], glo, ghi);
            up2(aB[k], blo, bhi);
            float il = 1.0f / wlo, ih = 1.0f / whi;
            int gr = rowBase + r0t + k;
            float* o0 = ob + gr * W_IMG + gc;
            *(float2*)(o0)             = make_float2(fminf(fmaxf(rlo * il, 0.f), 1.f),
                                                     fminf(fmaxf(rhi * ih, 0.f), 1.f));
            *(float2*)(o0 + PLANE)     = make_float2(fminf(fmaxf(glo * il, 0.f), 1.f),
                                                     fminf(fmaxf(ghi * ih, 0.f), 1.f));
            *(float2*)(o0 + 2 * PLANE) = make_float2(fminf(fmaxf(blo * il, 0.f), 1.f),
                                                     fminf(fmaxf(bhi * ih, 0.f), 1.f));
        }
    }
}

extern "C" void kernel_launch(void* const* d_in, const int* in_sizes, int n_in,
                              void* d_out, int out_size)
{
    (void)in_sizes; (void)n_in; (void)out_size;
    const float* x = (const float*)d_in[0];
    float* out = (float*)d_out;

    dim3 block(32, WARPS, 1);
    dim3 grid((W_IMG + OUT_COLS - 1) / OUT_COLS,   // 9 (last tile wraps; duplicate
              W_IMG / TILE_ROWS,                   //    writes are bitwise identical)
              2);                                  // 9*32*2 = 576 = one wave @4/SM
    nlm_kernel<<<grid, block>>>(x, out);
}